// round 2
// baseline (speedup 1.0000x reference)
#include <cuda_runtime.h>
#include <cuda_bf16.h>
#include <math.h>

#define NN 4096
#define EE 65536
#define HH 128
#define RR 32
#define NH (NN*HH)

// ---------------- scratch (device globals; no runtime allocation) ----------------
__device__ __align__(16) float4 g_acc4[NH*3];   // per (n,h): {i0,ax,ay,az},{sxx,sxy,sxz,syy},{syz,szz,0,0}
__device__ __align__(16) float g_cm[10*NH];     // comp-major copies for the mix GEMM
__device__ __align__(16) float g_T1[128*HH];
__device__ __align__(16) float g_T2[128*HH];
__device__ __align__(16) float g_nrm[NH];
__device__ __align__(16) float g_h[NN*256];
__device__ __align__(16) float g_scal[NN*384];
__device__ __align__(16) float g_mix[10*NH];
__device__ __align__(16) float g_x[NN*384];
__device__ __align__(16) float g_xln[NN*384];
__device__ __align__(16) float g_s1[NN*HH];
__device__ __align__(16) float g_s2[NN*64];

// Device-side resolution of scratch buffers. NEVER pass __device__ globals as
// kernel arguments from host code (host sees the shadow symbol, not the device
// address) — that was the Round-1 bug.
__device__ __forceinline__ float* gptr(int id) {
    switch (id) {
        case 0: return g_nrm;
        case 1: return g_h;
        case 2: return g_scal;
        case 3: return g_xln;
        case 4: return g_s1;
        case 5: return g_s2;
    }
    return nullptr;
}

__device__ __forceinline__ float warp_sum(float v) {
    #pragma unroll
    for (int o = 16; o > 0; o >>= 1) v += __shfl_xor_sync(0xffffffffu, v, o);
    return v;
}

// ---------------- zero accumulators ----------------
__global__ void k_zero() {
    int i = blockIdx.x * blockDim.x + threadIdx.x;
    if (i < NH*3) g_acc4[i] = make_float4(0.f, 0.f, 0.f, 0.f);
}

// ---------------- T1/T2 tables: fold emb + emb2 (+bias) over the 128 atom types ----------------
__global__ void k_tables(const float* __restrict__ emb_w, const float* __restrict__ emb2_w,
                         const float* __restrict__ emb2_b) {
    int t = blockIdx.x;          // atom type 0..127
    int h = threadIdx.x;         // 0..127
    __shared__ float se[128];
    se[h] = emb_w[t*HH + h];
    __syncthreads();
    float s1 = emb2_b[h], s2 = 0.f;
    #pragma unroll 8
    for (int k = 0; k < 128; k++) {
        s1 = fmaf(emb2_w[h*256 + k],       se[k], s1);
        s2 = fmaf(emb2_w[h*256 + 128 + k], se[k], s2);
    }
    g_T1[t*HH + h] = s1;
    g_T2[t*HH + h] = s2;
}

// ---------------- edge kernel: per-edge weights + vector-atomic scatter ----------------
__global__ void k_edge(const float* __restrict__ edge_vec,
                       const int*   __restrict__ eidx,
                       const int*   __restrict__ z,
                       const float* __restrict__ dp1w, const float* __restrict__ dp1b,
                       const float* __restrict__ dp2w, const float* __restrict__ dp2b,
                       const float* __restrict__ dp3w, const float* __restrict__ dp3b,
                       float m0, float dm, float beta)
{
    __shared__ float sdp[3][RR*HH];          // [ch][r*128+h]  — conflict-free compute reads
    int tid = threadIdx.x;
    for (int i = tid; i < RR*HH; i += blockDim.x) {
        int r = i >> 7, h = i & 127;
        sdp[0][i] = dp1w[h*RR + r];
        sdp[1][i] = dp2w[h*RR + r];
        sdp[2][i] = dp3w[h*RR + r];
    }
    __syncthreads();

    int lane = tid & 31;
    int warp = tid >> 5;
    int gw  = blockIdx.x * (blockDim.x >> 5) + warp;
    int nwp = gridDim.x * (blockDim.x >> 5);
    const float PI_CU = 3.14159265358979f / 4.5f;
    const float ALPHA = 5.0f / 4.5f;

    float b1[4], b2[4], b3[4];
    #pragma unroll
    for (int j = 0; j < 4; j++) {
        b1[j] = dp1b[lane + 32*j];
        b2[j] = dp2b[lane + 32*j];
        b3[j] = dp3b[lane + 32*j];
    }

    for (int b = gw; b < (EE/4); b += nwp) {
        float rbf[4], cutv[4], vx[4], vy[4], vz[4];
        int nsrc[4], zs[4], zt[4];
        #pragma unroll
        for (int e = 0; e < 4; e++) {
            int eid = b*4 + e;
            float ex = __ldg(&edge_vec[eid*3+0]);
            float ey = __ldg(&edge_vec[eid*3+1]);
            float ez = __ldg(&edge_vec[eid*3+2]);
            float d  = sqrtf(ex*ex + ey*ey + ez*ez);
            float inv = 1.0f / d;
            float cut = (d < 4.5f) ? 0.5f*(cosf(PI_CU*d) + 1.0f) : 0.0f;
            float expd = __expf(-ALPHA*d);
            float df = expd - (m0 + dm*(float)lane);
            rbf[e]  = cut * __expf(-beta*df*df);
            cutv[e] = cut;
            vx[e] = ex*inv; vy[e] = ey*inv; vz[e] = ez*inv;
            nsrc[e] = __ldg(&eidx[eid]);
            int tdst = __ldg(&eidx[EE + eid]);
            zs[e] = __ldg(&z[nsrc[e]]);
            zt[e] = __ldg(&z[tdst]);
        }

        float p[3][4][4];                                  // [ch][j][e]
        #pragma unroll
        for (int j = 0; j < 4; j++)
            #pragma unroll
            for (int e = 0; e < 4; e++) { p[0][j][e]=b1[j]; p[1][j][e]=b2[j]; p[2][j][e]=b3[j]; }

        #pragma unroll 2
        for (int r = 0; r < RR; r++) {
            float rv[4];
            #pragma unroll
            for (int e = 0; e < 4; e++) rv[e] = __shfl_sync(0xffffffffu, rbf[e], r);
            #pragma unroll
            for (int j = 0; j < 4; j++) {
                int hi = r*HH + lane + 32*j;
                float a1 = sdp[0][hi];
                float a2 = sdp[1][hi];
                float a3 = sdp[2][hi];
                #pragma unroll
                for (int e = 0; e < 4; e++) {
                    p[0][j][e] = fmaf(a1, rv[e], p[0][j][e]);
                    p[1][j][e] = fmaf(a2, rv[e], p[1][j][e]);
                    p[2][j][e] = fmaf(a3, rv[e], p[2][j][e]);
                }
            }
        }

        #pragma unroll
        for (int e = 0; e < 4; e++) {
            float cut = cutv[e];
            if (cut == 0.0f) continue;                      // uniform across warp
            float x = vx[e], y = vy[e], zc = vz[e];
            float tr3 = (x*x + y*y + zc*zc) * (1.0f/3.0f);
            float oxx = x*x - tr3, oyy = y*y - tr3, ozz = zc*zc - tr3;
            float oxy = x*y, oxz = x*zc, oyz = y*zc;
            int zr1 = zs[e]*HH, zr2 = zt[e]*HH;
            int nb  = nsrc[e]*HH;
            #pragma unroll
            for (int j = 0; j < 4; j++) {
                int h = lane + 32*j;
                float c  = cut * (__ldg(&g_T1[zr1 + h]) + __ldg(&g_T2[zr2 + h]));
                float w1 = p[0][j][e]*c, w2 = p[1][j][e]*c, w3 = p[2][j][e]*c;
                float4* bp = g_acc4 + (size_t)(nb + h)*3;
                atomicAdd(bp + 0, make_float4(w1,     w2*x,   w2*y,   w2*zc));
                atomicAdd(bp + 1, make_float4(w3*oxx, w3*oxy, w3*oxz, w3*oyy));
                atomicAdd(bp + 2, make_float4(w3*oyz, w3*ozz, 0.f,    0.f));
            }
        }
    }
}

// ---------------- tensor norm + layernorm(H) + comp-major split ----------------
__global__ void k_tnln(const float* __restrict__ ig, const float* __restrict__ ib) {
    int w = (blockIdx.x * blockDim.x + threadIdx.x) >> 5;
    if (w >= NN) return;
    int lane = threadIdx.x & 31;
    float tn[4];
    #pragma unroll
    for (int j = 0; j < 4; j++) {
        int h = lane + 32*j;
        size_t o = (size_t)w*HH + h;
        const float4* ap = g_acc4 + o*3;
        float4 q1 = ap[0], q2 = ap[1], q3 = ap[2];
        g_cm[0*NH+o]=q1.x; g_cm[1*NH+o]=q1.y; g_cm[2*NH+o]=q1.z; g_cm[3*NH+o]=q1.w;
        g_cm[4*NH+o]=q2.x; g_cm[5*NH+o]=q2.y; g_cm[6*NH+o]=q2.z; g_cm[7*NH+o]=q2.w;
        g_cm[8*NH+o]=q3.x; g_cm[9*NH+o]=q3.y;
        tn[j] = 3.f*q1.x*q1.x
              + 2.f*(q1.y*q1.y + q1.z*q1.z + q1.w*q1.w)
              + q2.x*q2.x + q2.w*q2.w + q3.y*q3.y
              + 2.f*(q2.y*q2.y + q2.z*q2.z + q3.x*q3.x);
    }
    float s = warp_sum(tn[0]+tn[1]+tn[2]+tn[3]);
    float mu = s * (1.0f/128.0f);
    float v = 0.f;
    #pragma unroll
    for (int j = 0; j < 4; j++) { float d = tn[j]-mu; v += d*d; }
    v = warp_sum(v) * (1.0f/128.0f);
    float rs = rsqrtf(v + 1e-5f);
    #pragma unroll
    for (int j = 0; j < 4; j++) {
        int h = lane + 32*j;
        g_nrm[(size_t)w*HH + h] = (tn[j]-mu)*rs*ig[h] + ib[h];
    }
}

// ---------------- generic fp32 tiled GEMM: C[n,o] = act(A[n,:K]·W[o,:K] + bias[o]) ----------------
template<int ACT>
__device__ __forceinline__ void gemm_core(const float* __restrict__ A, const float* __restrict__ W,
                                          const float* __restrict__ bias, float* __restrict__ C,
                                          int K, int O) {
    __shared__ __align__(16) float As[32*132];
    __shared__ __align__(16) float Ws[32*68];
    int tid = threadIdx.x;
    int tn = tid & 15, tm = tid >> 4;
    int rowBase = blockIdx.y * 128;
    int colBase = blockIdx.x * 64;
    float acc[8][4];
    #pragma unroll
    for (int i = 0; i < 8; i++)
        #pragma unroll
        for (int j = 0; j < 4; j++) acc[i][j] = 0.f;

    for (int k0 = 0; k0 < K; k0 += 32) {
        #pragma unroll
        for (int i = 0; i < 16; i++) {
            int lin = tid + i*256;
            int m = lin >> 5, k = lin & 31;
            As[k*132 + m] = A[(size_t)(rowBase + m)*K + k0 + k];
        }
        #pragma unroll
        for (int i = 0; i < 8; i++) {
            int lin = tid + i*256;
            int n = lin >> 5, k = lin & 31;
            Ws[k*68 + n] = W[(size_t)(colBase + n)*K + k0 + k];
        }
        __syncthreads();
        #pragma unroll 8
        for (int k = 0; k < 32; k++) {
            float4 a0 = *(const float4*)&As[k*132 + tm*8];
            float4 a1 = *(const float4*)&As[k*132 + tm*8 + 4];
            float4 bq = *(const float4*)&Ws[k*68 + tn*4];
            float av[8] = {a0.x,a0.y,a0.z,a0.w,a1.x,a1.y,a1.z,a1.w};
            float bv[4] = {bq.x,bq.y,bq.z,bq.w};
            #pragma unroll
            for (int i = 0; i < 8; i++)
                #pragma unroll
                for (int j = 0; j < 4; j++)
                    acc[i][j] = fmaf(av[i], bv[j], acc[i][j]);
        }
        __syncthreads();
    }
    #pragma unroll
    for (int i = 0; i < 8; i++) {
        int r = rowBase + tm*8 + i;
        float o4[4];
        #pragma unroll
        for (int j = 0; j < 4; j++) {
            int c = colBase + tn*4 + j;
            float v = acc[i][j];
            if (bias) v += __ldg(&bias[c]);
            if (ACT)  v = v / (1.0f + __expf(-v));
            o4[j] = v;
        }
        *(float4*)&C[(size_t)r*O + colBase + tn*4] = make_float4(o4[0],o4[1],o4[2],o4[3]);
    }
}

// A and C resolved device-side via gptr(); W/bias are real device pointers (harness inputs).
template<int ACT>
__global__ void k_gemm(int aId, const float* __restrict__ W,
                       const float* __restrict__ bias, int cId,
                       int K, int O) {
    gemm_core<ACT>(gptr(aId), W, bias, gptr(cId), K, O);
}

__global__ void k_gemm_mix(const float* __restrict__ lt0, const float* __restrict__ lt1,
                           const float* __restrict__ lt2) {
    int c = blockIdx.z;
    const float* A = g_cm + (size_t)c*NH;
    const float* W = (c == 0) ? lt0 : (c < 4 ? lt1 : lt2);
    float* C = g_mix + (size_t)c*NH;
    gemm_core<0>(A, W, nullptr, C, HH, HH);
}

// ---------------- combine: x = [3*I1^2, 2*|A1|^2, |S1|^2] * gates^2 ----------------
__global__ void k_combine() {
    int idx = blockIdx.x * blockDim.x + threadIdx.x;
    if (idx >= NH) return;
    int n = idx >> 7, g = idx & 127;
    float mi  = g_mix[0*NH+idx];
    float ax  = g_mix[1*NH+idx], ay = g_mix[2*NH+idx], az = g_mix[3*NH+idx];
    float sxx = g_mix[4*NH+idx], sxy = g_mix[5*NH+idx], sxz = g_mix[6*NH+idx];
    float syy = g_mix[7*NH+idx], syz = g_mix[8*NH+idx], szz = g_mix[9*NH+idx];
    float s0 = g_scal[n*384 + 3*g + 0];
    float s1 = g_scal[n*384 + 3*g + 1];
    float s2 = g_scal[n*384 + 3*g + 2];
    g_x[n*384 + g]       = 3.f*mi*mi*s0*s0;
    g_x[n*384 + 128 + g] = 2.f*(ax*ax + ay*ay + az*az)*s1*s1;
    g_x[n*384 + 256 + g] = (sxx*sxx + syy*syy + szz*szz
                            + 2.f*(sxy*sxy + sxz*sxz + syz*syz))*s2*s2;
}

// ---------------- layernorm over 3H=384 ----------------
__global__ void k_outln(const float* __restrict__ og, const float* __restrict__ ob) {
    int a = (blockIdx.x * blockDim.x + threadIdx.x) >> 5;
    if (a >= NN) return;
    int lane = threadIdx.x & 31;
    float xv[12];
    float s = 0.f;
    #pragma unroll
    for (int j = 0; j < 12; j++) {
        xv[j] = g_x[(size_t)a*384 + lane + 32*j];
        s += xv[j];
    }
    float mu = warp_sum(s) * (1.0f/384.0f);
    float v = 0.f;
    #pragma unroll
    for (int j = 0; j < 12; j++) { float d = xv[j]-mu; v += d*d; }
    v = warp_sum(v) * (1.0f/384.0f);
    float rs = rsqrtf(v + 1e-5f);
    #pragma unroll
    for (int j = 0; j < 12; j++) {
        int h = lane + 32*j;
        g_xln[(size_t)a*384 + h] = (xv[j]-mu)*rs*og[h] + ob[h];
    }
}

// ---------------- final per-atom dot: out[n] = silu(s2)·ol2_w + b ----------------
__global__ void k_final(const float* __restrict__ ol2w, const float* __restrict__ ol2b,
                        float* __restrict__ out) {
    int a = (blockIdx.x * blockDim.x + threadIdx.x) >> 5;
    if (a >= NN) return;
    int lane = threadIdx.x & 31;
    float v = g_s2[a*64 + lane]      * __ldg(&ol2w[lane])
            + g_s2[a*64 + lane + 32] * __ldg(&ol2w[lane + 32]);
    v = warp_sum(v);
    if (lane == 0) out[a] = v + ol2b[0];
}

// ---------------- launch ----------------
extern "C" void kernel_launch(void* const* d_in, const int* in_sizes, int n_in,
                              void* d_out, int out_size) {
    const float* edge_vec = (const float*)d_in[0];
    const float* emb_w    = (const float*)d_in[1];
    const float* emb2_w   = (const float*)d_in[2];
    const float* emb2_b   = (const float*)d_in[3];
    const float* dp1_w    = (const float*)d_in[4];
    const float* dp1_b    = (const float*)d_in[5];
    const float* dp2_w    = (const float*)d_in[6];
    const float* dp2_b    = (const float*)d_in[7];
    const float* dp3_w    = (const float*)d_in[8];
    const float* dp3_b    = (const float*)d_in[9];
    const float* lt0_w    = (const float*)d_in[10];
    const float* lt1_w    = (const float*)d_in[11];
    const float* lt2_w    = (const float*)d_in[12];
    const float* ls0_w    = (const float*)d_in[13];
    const float* ls0_b    = (const float*)d_in[14];
    const float* ls1_w    = (const float*)d_in[15];
    const float* ls1_b    = (const float*)d_in[16];
    const float* init_g   = (const float*)d_in[17];
    const float* init_b   = (const float*)d_in[18];
    const float* lin_w    = (const float*)d_in[19];
    const float* lin_b    = (const float*)d_in[20];
    const float* outn_g   = (const float*)d_in[21];
    const float* outn_b   = (const float*)d_in[22];
    const float* ol1_w    = (const float*)d_in[23];
    const float* ol1_b    = (const float*)d_in[24];
    const float* ol2_w    = (const float*)d_in[25];
    const float* ol2_b    = (const float*)d_in[26];
    const int*   z        = (const int*)d_in[27];
    const int*   eidx     = (const int*)d_in[28];
    float* out = (float*)d_out;

    float m0   = expf(-4.5f);
    float dm   = (1.0f - m0) / 31.0f;
    float tmp  = (2.0f/32.0f) * (1.0f - m0);
    float beta = 1.0f / (tmp*tmp);

    // phase 0: zero accumulators + type tables
    k_zero<<<(NH*3 + 255)/256, 256>>>();
    k_tables<<<128, 128>>>(emb_w, emb2_w, emb2_b);

    // phase 1: edge scatter
    k_edge<<<512, 256>>>(edge_vec, eidx, z,
                         dp1_w, dp1_b, dp2_w, dp2_b, dp3_w, dp3_b,
                         m0, dm, beta);

    // phase 2: tensor norm + LN(H)
    k_tnln<<<NN/8, 256>>>(init_g, init_b);

    // phase 3: gating MLP  (buffer ids: 0=g_nrm 1=g_h 2=g_scal 3=g_xln 4=g_s1 5=g_s2)
    k_gemm<1><<<dim3(256/64, NN/128), 256>>>(0, ls0_w, ls0_b, 1, 128, 256);
    k_gemm<1><<<dim3(384/64, NN/128), 256>>>(1, ls1_w, ls1_b, 2, 256, 384);

    // phase 4: channel mixing for all 10 tensor components
    k_gemm_mix<<<dim3(128/64, NN/128, 10), 256>>>(lt0_w, lt1_w, lt2_w);

    // phase 5: norms * gates -> x, LN(3H)
    k_combine<<<NH/256, 256>>>();
    k_outln<<<NN/8, 256>>>(outn_g, outn_b);

    // phase 6: output MLP
    k_gemm<1><<<dim3(128/64, NN/128), 256>>>(3, lin_w, lin_b, 4, 384, 128);
    k_gemm<1><<<dim3(64/64,  NN/128), 256>>>(4, ol1_w, ol1_b, 5, 128, 64);
    k_final<<<NN/8, 256>>>(ol2_w, ol2_b, out);
}